// round 7
// baseline (speedup 1.0000x reference)
#include <cuda_runtime.h>
#include <cuda_bf16.h>
#include <cstdint>

// Problem constants
#define MCC    10
#define INC    16
#define OUTC   32
#define HW_IN  128
#define HW_OUT 64
#define KTOT   144          // 3*3*16
#define NTOT   320

// Tiles: CTA = 160 channels (MMA-M) x 128 pixels (MMA-N), full K=144
#define THREADS 512
#define CH_TILE 160
#define PX_TILE 128
#define AKB     304         // padded K row stride in bytes (152 bf16 = 19*16B)

#define OFF_XHI 0
#define OFF_XLO (PX_TILE * AKB)
#define OFF_WHI (2 * PX_TILE * AKB)
#define OFF_WLO (2 * PX_TILE * AKB + CH_TILE * AKB)
#define SMEM_BYTES (2 * PX_TILE * AKB + 2 * CH_TILE * AKB)  // 175104

// Pre-split weights, [n][k] layout (n = mc*32+oc), k padded to 152
#define WKP 152
__device__ __nv_bfloat16 d_Wh[NTOT * WKP];
__device__ __nv_bfloat16 d_Wl[NTOT * WKP];

__device__ __forceinline__ uint32_t smem_u32(const void* p) {
    uint32_t a;
    asm("{ .reg .u64 t; cvta.to.shared.u64 t, %1; cvt.u32.u64 %0, t; }" : "=r"(a) : "l"(p));
    return a;
}
__device__ __forceinline__ void ldmx4(uint32_t addr, uint32_t &r0, uint32_t &r1,
                                      uint32_t &r2, uint32_t &r3) {
    asm volatile("ldmatrix.sync.aligned.m8n8.x4.shared.b16 {%0,%1,%2,%3}, [%4];"
                 : "=r"(r0), "=r"(r1), "=r"(r2), "=r"(r3) : "r"(addr));
}
__device__ __forceinline__ void mma16816(float* d, const uint32_t* a, const uint32_t* bb) {
    asm volatile(
        "mma.sync.aligned.m16n8k16.row.col.f32.bf16.bf16.f32 "
        "{%0,%1,%2,%3}, {%4,%5,%6,%7}, {%8,%9}, {%0,%1,%2,%3};"
        : "+f"(d[0]), "+f"(d[1]), "+f"(d[2]), "+f"(d[3])
        : "r"(a[0]), "r"(a[1]), "r"(a[2]), "r"(a[3]), "r"(bb[0]), "r"(bb[1]));
}
__device__ __forceinline__ void fast_sincos(float v, float &s, float &c) {
    float t = rintf(v * 0.15915494309189535f);
    float r = fmaf(t, -6.2831855f, v);
    r = fmaf(t, 1.7484555e-7f, r);
    s = __sinf(r);
    c = __cosf(r);
}

// ---------- weight materialization: DESTINATION-indexed (race-free) ----------
__global__ void prep_w_kernel(const float* __restrict__ mean,
                              const float* __restrict__ ls,
                              const float* __restrict__ eps) {
    int i = blockIdx.x * 256 + threadIdx.x;     // destination slot in [NTOT*WKP)
    if (i >= NTOT * WKP) return;
    int n  = i / WKP;          // n = mc*32 + oc
    int kk = i - n * WKP;      // 0..151
    float w = 0.f;
    if (kk < KTOT) {
        int mc = n >> 5;
        int oc = n & 31;
        float e = eps[(mc * KTOT + kk) * OUTC + oc];
        w = fmaf(e, expf(0.5f * ls[kk * OUTC + oc]), mean[kk * OUTC + oc]);
    }
    __nv_bfloat16 hi = __float2bfloat16_rn(w);
    __nv_bfloat16 lo = __float2bfloat16_rn(w - __bfloat162float(hi));
    d_Wh[i] = hi;
    d_Wl[i] = lo;
}

__global__ void __launch_bounds__(THREADS, 1)
conv_rff_hmma_kernel(const float* __restrict__ x,
                     const float* __restrict__ theta,
                     float* __restrict__ out) {
    extern __shared__ char sm[];
    const uint32_t smb = smem_u32(sm);

    const int tid   = threadIdx.x;
    const int wid   = tid >> 5;
    const int lane  = tid & 31;
    const int ntile = blockIdx.x;   // 0..1 (160-channel half)
    const int rg    = blockIdx.y;   // 0..31 (output-row pair)
    const int b     = blockIdx.z;   // 0..7

    // ---- Stage X (im2col pixels, bf16 hi/lo): X[px][k] ----
    {
        __nv_bfloat16* Xh = (__nv_bfloat16*)(sm + OFF_XHI);
        __nv_bfloat16* Xl = (__nv_bfloat16*)(sm + OFF_XLO);
        const float* xb = x + (size_t)b * INC * HW_IN * HW_IN;
        #pragma unroll 4
        for (int i = tid; i < PX_TILE * KTOT; i += THREADS) {   // 36 iters
            int m = i / KTOT;
            int k = i - m * KTOT;
            int kh  = k / 48;
            int rem = k - kh * 48;
            int kw  = rem >> 4;
            int c   = rem & 15;
            int oyp = m >> 6;
            int ox  = m & 63;
            int iy  = 4 * rg + 2 * oyp + kh - 1;
            int ix  = 2 * ox + kw - 1;
            float v = 0.f;
            if ((unsigned)iy < (unsigned)HW_IN && (unsigned)ix < (unsigned)HW_IN)
                v = xb[(c * HW_IN + iy) * HW_IN + ix];
            __nv_bfloat16 hi = __float2bfloat16_rn(v);
            __nv_bfloat16 lo = __float2bfloat16_rn(v - __bfloat162float(hi));
            *(__nv_bfloat16*)((char*)Xh + m * AKB + k * 2) = hi;
            *(__nv_bfloat16*)((char*)Xl + m * AKB + k * 2) = lo;
        }
    }
    // ---- Stage W: pure vectorized copy (pre-split, [n][k] padded 152) ----
    {
        const uint4* gh = (const uint4*)(d_Wh + (size_t)ntile * CH_TILE * WKP);
        const uint4* gl = (const uint4*)(d_Wl + (size_t)ntile * CH_TILE * WKP);
        for (int i = tid; i < CH_TILE * (AKB / 16); i += THREADS) {   // 3040 slots
            *(uint4*)(sm + OFF_WHI + i * 16) = gh[i];
            *(uint4*)(sm + OFF_WLO + i * 16) = gl[i];
        }
    }
    __syncthreads();

    // ---- Mainloop: warp tile 80ch x 16px; 3 splits x 9 k-chunks ----
    const int chbase = (wid >> 3) * 80;   // 0 or 80
    const int pxbase = (wid & 7) * 16;    // 0..112

    const uint32_t a_off = (uint32_t)((lane & 15) * AKB + (lane >> 4) * 16);
    const uint32_t b_off = (uint32_t)(((lane >> 4) * 8 + (lane & 7)) * AKB +
                                      ((lane >> 3) & 1) * 16);

    const uint32_t wbase_s[3] = { smb + OFF_WHI + chbase * AKB + a_off,
                                  smb + OFF_WHI + chbase * AKB + a_off,
                                  smb + OFF_WLO + chbase * AKB + a_off };
    const uint32_t xbase_s[3] = { smb + OFF_XHI + pxbase * AKB + b_off,
                                  smb + OFF_XLO + pxbase * AKB + b_off,
                                  smb + OFF_XHI + pxbase * AKB + b_off };

    float acc[5][2][4];
    #pragma unroll
    for (int mi = 0; mi < 5; ++mi)
        #pragma unroll
        for (int ni = 0; ni < 2; ++ni)
            #pragma unroll
            for (int c = 0; c < 4; ++c)
                acc[mi][ni][c] = 0.f;

    #pragma unroll
    for (int it = 0; it < 27; ++it) {
        const int s  = it / 9;
        const int kc = it - s * 9;
        const uint32_t kb = (uint32_t)kc * 32;
        uint32_t bfr[2][2];
        {
            uint32_t r0, r1, r2, r3;
            ldmx4(xbase_s[s] + kb, r0, r1, r2, r3);
            bfr[0][0] = r0; bfr[0][1] = r1;
            bfr[1][0] = r2; bfr[1][1] = r3;
        }
        #pragma unroll
        for (int mi = 0; mi < 5; ++mi) {
            uint32_t a[4];
            ldmx4(wbase_s[s] + mi * (16 * AKB) + kb, a[0], a[1], a[2], a[3]);
            mma16816(acc[mi][0], a, bfr[0]);
            mma16816(acc[mi][1], a, bfr[1]);
        }
    }

    // ---- Epilogue: scale*{cos,sin}, float2 stores ----
    const float scale = expf(0.5f * theta[0]) * 0.0027621358640644f; // 1/sqrt(32*64*64)
    const int l2 = lane >> 2;
    const int l3 = lane & 3;

    #pragma unroll
    for (int mi = 0; mi < 5; ++mi) {
        #pragma unroll
        for (int msub = 0; msub < 2; ++msub) {
            int ch  = chbase + mi * 16 + msub * 8 + l2;
            int ngl = ntile * CH_TILE + ch;              // global channel [0,320)
            int chan = (ngl >> 5) * 64 + (ngl & 31);     // mc*64 + oc
            float* basec = out + ((size_t)(b * (MCC * 2 * OUTC) + chan)) * (HW_OUT * HW_OUT);
            float* bases = basec + (size_t)OUTC * HW_OUT * HW_OUT;
            #pragma unroll
            for (int ni = 0; ni < 2; ++ni) {
                int px = pxbase + ni * 8 + 2 * l3;
                int oy = 2 * rg + (px >> 6);
                int ox = px & 63;
                float v0 = acc[mi][ni][msub * 2 + 0];
                float v1 = acc[mi][ni][msub * 2 + 1];
                float s0, c0, s1, c1;
                fast_sincos(v0, s0, c0);
                fast_sincos(v1, s1, c1);
                *(float2*)(basec + oy * HW_OUT + ox) = make_float2(scale * c0, scale * c1);
                *(float2*)(bases + oy * HW_OUT + ox) = make_float2(scale * s0, scale * s1);
            }
        }
    }
}

extern "C" void kernel_launch(void* const* d_in, const int* in_sizes, int n_in,
                              void* d_out, int out_size) {
    const float* x     = (const float*)d_in[0];
    const float* theta = (const float*)d_in[1];
    const float* mean  = (const float*)d_in[2];
    const float* ls    = (const float*)d_in[3];
    const float* eps   = (const float*)d_in[4];
    float* out = (float*)d_out;

    prep_w_kernel<<<(NTOT * WKP + 255) / 256, 256>>>(mean, ls, eps);

    cudaFuncSetAttribute(conv_rff_hmma_kernel,
                         cudaFuncAttributeMaxDynamicSharedMemorySize, SMEM_BYTES);
    dim3 grid(2, 32, 8);   // n-half, row-pair, batch
    conv_rff_hmma_kernel<<<grid, THREADS, SMEM_BYTES>>>(x, theta, out);
}

// round 8
// speedup vs baseline: 2.2447x; 2.2447x over previous
#include <cuda_runtime.h>
#include <cuda_bf16.h>
#include <cstdint>

// Problem constants
#define MCC    10
#define INC    16
#define OUTC   32
#define HW_IN  128
#define HW_OUT 64
#define KTOT   144          // 3*3*16
#define NTOT   320
#define NPX    32768        // total output pixels (8 * 64 * 64)

// Tiles: CTA = 64 channels x 96 pixels, 192 threads, 6 warps of 32x32
#define THREADS 192
#define CH_CTA  64
#define PX_CTA  96
#define AKB     304         // K row stride in bytes (152 bf16 = 19*16B, conflict-free)
#define PXTILES 342         // ceil(32768 / 96)

#define X_BYTES (PX_CTA * AKB)          // 29184
#define W_BYTES (CH_CTA * AKB)          // 19456
#define OFF_XHI 0
#define OFF_XLO (X_BYTES)
#define OFF_WHI (2 * X_BYTES)
#define OFF_WLO (2 * X_BYTES + W_BYTES)
#define SMEM_BYTES (2 * X_BYTES + 2 * W_BYTES)   // 97280 -> 2 CTAs/SM

// Pre-split weights, [n][k] layout (n = mc*32+oc), k padded to 152
#define WKP 152
__device__ __nv_bfloat16 d_Wh[NTOT * WKP];
__device__ __nv_bfloat16 d_Wl[NTOT * WKP];

__device__ __forceinline__ uint32_t smem_u32(const void* p) {
    uint32_t a;
    asm("{ .reg .u64 t; cvta.to.shared.u64 t, %1; cvt.u32.u64 %0, t; }" : "=r"(a) : "l"(p));
    return a;
}
__device__ __forceinline__ void ldmx4(uint32_t addr, uint32_t &r0, uint32_t &r1,
                                      uint32_t &r2, uint32_t &r3) {
    asm volatile("ldmatrix.sync.aligned.m8n8.x4.shared.b16 {%0,%1,%2,%3}, [%4];"
                 : "=r"(r0), "=r"(r1), "=r"(r2), "=r"(r3) : "r"(addr));
}
__device__ __forceinline__ void mma16816(float* d, const uint32_t* a, const uint32_t* bb) {
    asm volatile(
        "mma.sync.aligned.m16n8k16.row.col.f32.bf16.bf16.f32 "
        "{%0,%1,%2,%3}, {%4,%5,%6,%7}, {%8,%9}, {%0,%1,%2,%3};"
        : "+f"(d[0]), "+f"(d[1]), "+f"(d[2]), "+f"(d[3])
        : "r"(a[0]), "r"(a[1]), "r"(a[2]), "r"(a[3]), "r"(bb[0]), "r"(bb[1]));
}
__device__ __forceinline__ void fast_sincos(float v, float &s, float &c) {
    float t = rintf(v * 0.15915494309189535f);
    float r = fmaf(t, -6.2831855f, v);
    r = fmaf(t, 1.7484555e-7f, r);
    s = __sinf(r);
    c = __cosf(r);
}
__device__ __forceinline__ uint16_t bfbits(__nv_bfloat16 h) {
    uint16_t u; *(__nv_bfloat16*)&u = h; return u;
}

// ---------- weight materialization: DESTINATION-indexed (race-free) ----------
__global__ void prep_w_kernel(const float* __restrict__ mean,
                              const float* __restrict__ ls,
                              const float* __restrict__ eps) {
    int i = blockIdx.x * 256 + threadIdx.x;     // destination slot in [NTOT*WKP)
    if (i >= NTOT * WKP) return;
    int n  = i / WKP;          // n = mc*32 + oc
    int kk = i - n * WKP;      // 0..151
    float w = 0.f;
    if (kk < KTOT) {
        int mc = n >> 5;
        int oc = n & 31;
        float e = eps[(mc * KTOT + kk) * OUTC + oc];
        w = fmaf(e, expf(0.5f * ls[kk * OUTC + oc]), mean[kk * OUTC + oc]);
    }
    __nv_bfloat16 hi = __float2bfloat16_rn(w);
    __nv_bfloat16 lo = __float2bfloat16_rn(w - __bfloat162float(hi));
    d_Wh[i] = hi;
    d_Wl[i] = lo;
}

__global__ void __launch_bounds__(THREADS, 2)
conv_rff_hmma_kernel(const float* __restrict__ x,
                     const float* __restrict__ theta,
                     float* __restrict__ out) {
    extern __shared__ char sm[];
    const uint32_t smb = smem_u32(sm);

    const int tid   = threadIdx.x;
    const int wid   = tid >> 5;
    const int lane  = tid & 31;
    const int ntile = blockIdx.x;          // 0..4 (64-channel slab)
    const int px0   = blockIdx.y * PX_CTA; // flat pixel base

    // ---- Stage X (im2col, bf16 hi/lo) in k-quads, packed 8B stores ----
    {
        char* Xh = sm + OFF_XHI;
        char* Xl = sm + OFF_XLO;
        #pragma unroll 3
        for (int i = tid; i < PX_CTA * (KTOT / 4); i += THREADS) {   // 3456 -> 18 iters
            int q  = i / PX_CTA;        // k-quad 0..35
            int px = i - q * PX_CTA;
            int k0 = q * 4;
            int kh  = k0 / 48;
            int rem = k0 - kh * 48;
            int kw  = rem >> 4;
            int c0  = rem & 15;         // quads never straddle (kh,kw): 16 % 4 == 0
            int gp  = px0 + px;
            int b   = gp >> 12;
            int oy  = (gp >> 6) & 63;
            int ox  = gp & 63;
            int iy  = 2 * oy + kh - 1;
            int ix  = 2 * ox + kw - 1;
            bool valid = (gp < NPX) && ((unsigned)iy < (unsigned)HW_IN)
                                     && ((unsigned)ix < (unsigned)HW_IN);
            const float* xp = x + (((size_t)b * INC + c0) * HW_IN + iy) * HW_IN + ix;
            float v[4];
            #pragma unroll
            for (int j = 0; j < 4; ++j)
                v[j] = valid ? xp[(size_t)j * HW_IN * HW_IN] : 0.f;
            uint16_t hu[4], lu[4];
            #pragma unroll
            for (int j = 0; j < 4; ++j) {
                __nv_bfloat16 h = __float2bfloat16_rn(v[j]);
                __nv_bfloat16 l = __float2bfloat16_rn(v[j] - __bfloat162float(h));
                hu[j] = bfbits(h); lu[j] = bfbits(l);
            }
            uint32_t off = (uint32_t)(px * AKB + k0 * 2);
            *(uint2*)(Xh + off) = make_uint2((uint32_t)hu[0] | ((uint32_t)hu[1] << 16),
                                             (uint32_t)hu[2] | ((uint32_t)hu[3] << 16));
            *(uint2*)(Xl + off) = make_uint2((uint32_t)lu[0] | ((uint32_t)lu[1] << 16),
                                             (uint32_t)lu[2] | ((uint32_t)lu[3] << 16));
        }
    }
    // ---- Stage W: vectorized copy (pre-split, [n][k] stride 304 B) ----
    {
        const uint4* gh = (const uint4*)(d_Wh + (size_t)ntile * CH_CTA * WKP);
        const uint4* gl = (const uint4*)(d_Wl + (size_t)ntile * CH_CTA * WKP);
        for (int i = tid; i < W_BYTES / 16; i += THREADS) {   // 1216 slots
            *(uint4*)(sm + OFF_WHI + i * 16) = gh[i];
            *(uint4*)(sm + OFF_WLO + i * 16) = gl[i];
        }
    }
    __syncthreads();

    // ---- Mainloop: 6 warps, warp tile 32ch x 32px; 3 splits x 9 k-chunks ----
    const int chbase = (wid & 1) * 32;    // 0 or 32
    const int pxw    = (wid >> 1) * 32;   // 0, 32, 64

    const uint32_t a_off = (uint32_t)((lane & 15) * AKB + (lane >> 4) * 16);
    const uint32_t b_off = (uint32_t)(((lane >> 4) * 8 + (lane & 7)) * AKB +
                                      ((lane >> 3) & 1) * 16);

    const uint32_t wbase_s[3] = { smb + OFF_WHI + chbase * AKB + a_off,
                                  smb + OFF_WHI + chbase * AKB + a_off,
                                  smb + OFF_WLO + chbase * AKB + a_off };
    const uint32_t xbase_s[3] = { smb + OFF_XHI + pxw * AKB + b_off,
                                  smb + OFF_XLO + pxw * AKB + b_off,
                                  smb + OFF_XHI + pxw * AKB + b_off };

    float acc[2][4][4];
    #pragma unroll
    for (int mi = 0; mi < 2; ++mi)
        #pragma unroll
        for (int ni = 0; ni < 4; ++ni)
            #pragma unroll
            for (int c = 0; c < 4; ++c)
                acc[mi][ni][c] = 0.f;

    #pragma unroll
    for (int it = 0; it < 27; ++it) {
        const int s  = it / 9;
        const int kc = it - s * 9;
        const uint32_t kb = (uint32_t)kc * 32;
        uint32_t bfr[4][2];
        {
            uint32_t r0, r1, r2, r3;
            ldmx4(xbase_s[s] + kb, r0, r1, r2, r3);
            bfr[0][0] = r0; bfr[0][1] = r1;
            bfr[1][0] = r2; bfr[1][1] = r3;
            ldmx4(xbase_s[s] + 16 * AKB + kb, r0, r1, r2, r3);
            bfr[2][0] = r0; bfr[2][1] = r1;
            bfr[3][0] = r2; bfr[3][1] = r3;
        }
        uint32_t a0[4], a1[4];
        ldmx4(wbase_s[s] + kb, a0[0], a0[1], a0[2], a0[3]);
        ldmx4(wbase_s[s] + 16 * AKB + kb, a1[0], a1[1], a1[2], a1[3]);
        #pragma unroll
        for (int ni = 0; ni < 4; ++ni) {
            mma16816(acc[0][ni], a0, bfr[ni]);
            mma16816(acc[1][ni], a1, bfr[ni]);
        }
    }

    // ---- Epilogue: scale*{cos,sin}, predicated float2 stores ----
    const float scale = expf(0.5f * theta[0]) * 0.0027621358640644f; // 1/sqrt(32*64*64)
    const int l2 = lane >> 2;
    const int l3 = lane & 3;

    #pragma unroll
    for (int mi = 0; mi < 2; ++mi) {
        #pragma unroll
        for (int msub = 0; msub < 2; ++msub) {
            int ch  = chbase + mi * 16 + msub * 8 + l2;
            int ngl = ntile * CH_CTA + ch;               // global channel [0,320)
            int chan = (ngl >> 5) * 64 + (ngl & 31);     // mc*64 + oc
            #pragma unroll
            for (int ni = 0; ni < 4; ++ni) {
                int gp = px0 + pxw + ni * 8 + 2 * l3;
                if (gp >= NPX) continue;
                int b  = gp >> 12;
                int oy = (gp >> 6) & 63;
                int ox = gp & 63;
                float* basec = out + ((size_t)(b * (MCC * 2 * OUTC) + chan)) * (HW_OUT * HW_OUT)
                                   + oy * HW_OUT + ox;
                float* bases = basec + (size_t)OUTC * HW_OUT * HW_OUT;
                float v0 = acc[mi][ni][msub * 2 + 0];
                float v1 = acc[mi][ni][msub * 2 + 1];
                float s0, c0, s1, c1;
                fast_sincos(v0, s0, c0);
                fast_sincos(v1, s1, c1);
                *(float2*)basec = make_float2(scale * c0, scale * c1);
                *(float2*)bases = make_float2(scale * s0, scale * s1);
            }
        }
    }
}

extern "C" void kernel_launch(void* const* d_in, const int* in_sizes, int n_in,
                              void* d_out, int out_size) {
    const float* x     = (const float*)d_in[0];
    const float* theta = (const float*)d_in[1];
    const float* mean  = (const float*)d_in[2];
    const float* ls    = (const float*)d_in[3];
    const float* eps   = (const float*)d_in[4];
    float* out = (float*)d_out;

    prep_w_kernel<<<(NTOT * WKP + 255) / 256, 256>>>(mean, ls, eps);

    cudaFuncSetAttribute(conv_rff_hmma_kernel,
                         cudaFuncAttributeMaxDynamicSharedMemorySize, SMEM_BYTES);
    dim3 grid(5, PXTILES, 1);   // 64-ch slab x 342 pixel tiles
    conv_rff_hmma_kernel<<<grid, THREADS, SMEM_BYTES>>>(x, theta, out);
}